// round 1
// baseline (speedup 1.0000x reference)
#include <cuda_runtime.h>
#include <cstdint>

#define HDIM 4096
#define VOCAB 50257
#define SEQL 2048
#define TOPK 50
#define MINKEEP 5
#define HSPLIT 4
#define HCHUNK (HDIM / HSPLIT)          // 1024
#define NVBLK ((VOCAB + 255) / 256)     // 197
#define CAP 1024

__device__ float g_x[HDIM];
__device__ float g_part[HSPLIT * VOCAB];
__device__ float g_logits[VOCAB];
__device__ unsigned int g_hist[65536];
__device__ float g_topv[TOPK];
__device__ int   g_topi[TOPK];

__device__ __forceinline__ unsigned int fkey(float f) {
    unsigned int u = __float_as_uint(f);
    return (u & 0x80000000u) ? ~u : (u | 0x80000000u);
}

// ---------------- LayerNorm (one block) ----------------
__global__ void ln_kernel(const float* __restrict__ hin,
                          const float* __restrict__ gamma,
                          const float* __restrict__ beta) {
    __shared__ float xs[HDIM];
    __shared__ float red[1024];
    int tid = threadIdx.x;
    float s = 0.f;
    for (int i = tid; i < HDIM; i += 1024) { float v = hin[i]; xs[i] = v; s += v; }
    red[tid] = s; __syncthreads();
    for (int o = 512; o > 0; o >>= 1) { if (tid < o) red[tid] += red[tid + o]; __syncthreads(); }
    float mu = red[0] / HDIM;
    __syncthreads();
    float sq = 0.f;
    for (int i = tid; i < HDIM; i += 1024) { float d = xs[i] - mu; sq += d * d; }
    red[tid] = sq; __syncthreads();
    for (int o = 512; o > 0; o >>= 1) { if (tid < o) red[tid] += red[tid + o]; __syncthreads(); }
    float rstd = rsqrtf(red[0] / HDIM + 1e-5f);
    for (int i = tid; i < HDIM; i += 1024)
        g_x[i] = (xs[i] - mu) * rstd * gamma[i] + beta[i];
}

// ---------------- GEMV: one vocab column per thread, H split 4-ways ----------------
__global__ void gemv_kernel(const float* __restrict__ W) {
    __shared__ float xs[HCHUNK];
    int hb = blockIdx.y;
    int h0 = hb * HCHUNK;
    for (int i = threadIdx.x; i < HCHUNK; i += 256) xs[i] = g_x[h0 + i];
    __syncthreads();
    int v = blockIdx.x * 256 + threadIdx.x;
    if (v >= VOCAB) return;
    const float* wp = W + (size_t)h0 * VOCAB + v;
    float a0 = 0.f, a1 = 0.f, a2 = 0.f, a3 = 0.f;
#pragma unroll 4
    for (int i = 0; i < HCHUNK; i += 4) {
        a0 += xs[i]     * wp[0];
        a1 += xs[i + 1] * wp[(size_t)VOCAB];
        a2 += xs[i + 2] * wp[2 * (size_t)VOCAB];
        a3 += xs[i + 3] * wp[3 * (size_t)VOCAB];
        wp += 4 * (size_t)VOCAB;
    }
    g_part[hb * VOCAB + v] = (a0 + a1) + (a2 + a3);
}

// deterministic partial-sum combine
__global__ void combine_kernel() {
    int v = blockIdx.x * 256 + threadIdx.x;
    if (v < VOCAB)
        g_logits[v] = (g_part[v] + g_part[VOCAB + v]) +
                      (g_part[2 * VOCAB + v] + g_part[3 * VOCAB + v]);
}

// ---------------- repetition penalty (snapshot gather -> barrier -> scatter) ----------------
__global__ void penalty_kernel(const void* __restrict__ ids_raw,
                               const float* __restrict__ pen) {
    __shared__ int bad;                       // int64-vs-int32 detection
    int tid = threadIdx.x;
    if (tid == 0) bad = 0;
    __syncthreads();
    const long long* ll = (const long long*)ids_raw;
    long long probe = ll[tid];                // first 8KB: in-bounds either way
    if (probe < 0 || probe >= VOCAB) atomicOr(&bad, 1);
    __syncthreads();
    int is64 = (bad == 0);

    long long id0, id1;
    if (is64) { id0 = ll[tid]; id1 = ll[tid + 1024]; }
    else {
        const int* ii = (const int*)ids_raw;
        id0 = ii[tid]; id1 = ii[tid + 1024];
    }
    float p = pen[0];
    float l0 = g_logits[id0], l1 = g_logits[id1];
    float v0 = (l0 < 0.f) ? l0 * p : l0 / p;
    float v1 = (l1 < 0.f) ? l1 * p : l1 / p;
    __syncthreads();                          // all gathers before any scatter
    g_logits[id0] = v0;
    g_logits[id1] = v1;
}

// ---------------- top-k: 16-bit key histogram ----------------
__global__ void histzero_kernel() {
    int i = blockIdx.x * 256 + threadIdx.x;
    if (i < 65536) g_hist[i] = 0u;
}

__global__ void hist_kernel() {
    int v = blockIdx.x * 256 + threadIdx.x;
    if (v < VOCAB) atomicAdd(&g_hist[fkey(g_logits[v]) >> 16], 1u);
}

__global__ void topk_kernel() {
    __shared__ unsigned int chunksum[1024];
    __shared__ int shB;
    __shared__ int cnt;
    __shared__ float cv[CAP];
    __shared__ int   ci[CAP];
    int tid = threadIdx.x;
    unsigned s = 0;
    int base = tid * 64;
    for (int j = 0; j < 64; j++) s += g_hist[base + j];
    chunksum[tid] = s;
    if (tid == 0) cnt = 0;
    __syncthreads();
    if (tid == 0) {
        unsigned acc = 0;
        int t = 1023;
        for (; t > 0; --t) {
            if (acc + chunksum[t] >= (unsigned)TOPK) break;
            acc += chunksum[t];
        }
        int B = t * 64;
        for (int b = t * 64 + 63; b >= t * 64; --b) {
            unsigned c = g_hist[b];
            if (acc + c >= (unsigned)TOPK) { B = b; break; }
            acc += c;
        }
        shB = B;
    }
    __syncthreads();
    unsigned Bf = (unsigned)shB << 16;
    for (int i = tid; i < VOCAB; i += 1024) {
        float f = g_logits[i];
        if (fkey(f) >= Bf) {
            int p = atomicAdd(&cnt, 1);
            if (p < CAP) { cv[p] = f; ci[p] = i; }
        }
    }
    __syncthreads();
    int n = min(cnt, CAP);
    if (tid < n) {
        float v = cv[tid]; int ix = ci[tid];
        int r = 0;
        for (int j = 0; j < n; j++) {
            float vj = cv[j];
            if (vj > v || (vj == v && ci[j] < ix)) r++;
        }
        if (r < TOPK) { g_topv[r] = v; g_topi[r] = ix; }
    }
}

// ---------------- temperature / top-p sampling head ----------------
__global__ void sample_kernel(const float* __restrict__ tp_,
                              const float* __restrict__ temp_,
                              float* __restrict__ out, int out_size) {
    if (threadIdx.x != 0) return;
    float t = temp_[0], tp = tp_[0];
    float x[TOPK], p[TOPK], q[TOPK];
    for (int i = 0; i < TOPK; i++) x[i] = g_topv[i] / t;
    float m = x[0];                  // sorted descending -> max is first
    float s = 0.f;
    for (int i = 0; i < TOPK; i++) { p[i] = expf(x[i] - m); s += p[i]; }
    float cum = 0.f, s2 = 0.f;
    for (int i = 0; i < TOPK; i++) {
        cum += p[i] / s;             // inclusive cumsum of softmax
        bool keep = (cum < tp) || (i < MINKEEP);
        float f = keep ? x[i] : -1000.0f;
        q[i] = expf(f - m);
        s2 += q[i];
    }
    for (int i = 0; i < TOPK; i++) out[i] = q[i] / s2;
    if (out_size >= 2 * TOPK)
        for (int i = 0; i < TOPK; i++) out[TOPK + i] = (float)g_topi[i];
}

extern "C" void kernel_launch(void* const* d_in, const int* in_sizes, int n_in,
                              void* d_out, int out_size) {
    const float* hidden = (const float*)d_in[0];
    const void*  ids    = d_in[1];                 // int64 or int32, detected on device
    const float* top_p  = (const float*)d_in[2];
    const float* temp   = (const float*)d_in[3];
    const float* pen    = (const float*)d_in[4];
    const float* gamma  = (const float*)d_in[5];
    const float* beta   = (const float*)d_in[6];
    const float* W      = (const float*)d_in[7];
    float* out = (float*)d_out;

    ln_kernel<<<1, 1024>>>(hidden, gamma, beta);
    histzero_kernel<<<256, 256>>>();
    dim3 g(NVBLK, HSPLIT);
    gemv_kernel<<<g, 256>>>(W);
    combine_kernel<<<NVBLK, 256>>>();
    penalty_kernel<<<1, 1024>>>(ids, pen);
    hist_kernel<<<NVBLK, 256>>>();
    topk_kernel<<<1, 1024>>>();
    sample_kernel<<<1, 32>>>(top_p, temp, out, out_size);
}

// round 3
// speedup vs baseline: 1.0705x; 1.0705x over previous
#include <cuda_runtime.h>
#include <cstdint>

#define HDIM 4096
#define VOCAB 50257
#define SEQL 2048
#define TOPK 50
#define MINKEEP 5
#define HSPLIT 4
#define HCHUNK (HDIM / HSPLIT)          // 1024
#define NVBLK ((VOCAB + 255) / 256)     // 197
#define CAP 2048
#define BMW ((VOCAB + 31) / 32)         // bitmap words

__device__ float g_x[HDIM];
__device__ float g_part[HSPLIT * VOCAB];
__device__ float g_logits[VOCAB];
__device__ unsigned int g_hist[65536];
__device__ unsigned int g_bitmap[BMW];
__device__ unsigned int g_Bf;
__device__ int g_cnt;
__device__ float g_cv[CAP];
__device__ int   g_ci[CAP];

__device__ __forceinline__ unsigned int fkey(float f) {
    unsigned int u = __float_as_uint(f);
    return (u & 0x80000000u) ? ~u : (u | 0x80000000u);
}

// ---------------- LayerNorm + penalty bitmap build (one block) ----------------
__global__ void ln_kernel(const float* __restrict__ hin,
                          const float* __restrict__ gamma,
                          const float* __restrict__ beta,
                          const void* __restrict__ ids_raw) {
    __shared__ float xs[HDIM];
    __shared__ float red[1024];
    __shared__ int bad;
    int tid = threadIdx.x;
    for (int i = tid; i < BMW; i += 1024) g_bitmap[i] = 0u;
    if (tid == 0) bad = 0;

    float s = 0.f;
    for (int i = tid; i < HDIM; i += 1024) { float v = hin[i]; xs[i] = v; s += v; }
    red[tid] = s; __syncthreads();
    for (int o = 512; o > 0; o >>= 1) { if (tid < o) red[tid] += red[tid + o]; __syncthreads(); }
    float mu = red[0] / HDIM;
    __syncthreads();
    float sq = 0.f;
    for (int i = tid; i < HDIM; i += 1024) { float d = xs[i] - mu; sq += d * d; }
    red[tid] = sq; __syncthreads();
    for (int o = 512; o > 0; o >>= 1) { if (tid < o) red[tid] += red[tid + o]; __syncthreads(); }
    float rstd = rsqrtf(red[0] / HDIM + 1e-5f);
    for (int i = tid; i < HDIM; i += 1024)
        g_x[i] = (xs[i] - mu) * rstd * gamma[i] + beta[i];

    // ---- int64-vs-int32 detection (first 8KB valid under both) ----
    const long long* ll = (const long long*)ids_raw;
    long long probe = ll[tid];
    if (probe < 0 || probe >= VOCAB) atomicOr(&bad, 1);
    __syncthreads();
    int is64 = (bad == 0);
    long long id0, id1;
    if (is64) { id0 = ll[tid]; id1 = ll[tid + 1024]; }
    else {
        const int* ii = (const int*)ids_raw;
        id0 = ii[tid]; id1 = ii[tid + 1024];
    }
    atomicOr(&g_bitmap[(int)(id0 >> 5)], 1u << ((int)id0 & 31));
    atomicOr(&g_bitmap[(int)(id1 >> 5)], 1u << ((int)id1 & 31));
}

// ---------------- GEMV: 16 loads in flight per thread, single wave ----------------
__global__ void __launch_bounds__(256, 6) gemv_kernel(const float* __restrict__ W) {
    __shared__ float xs[HCHUNK];
    int tid = threadIdx.x;
    int hb = blockIdx.y;
    int h0 = hb * HCHUNK;
    // fused hist zeroing (hist consumed 2 launches later)
    int gb = (hb * gridDim.x + blockIdx.x) * 256 + tid;
    if (gb < 65536) g_hist[gb] = 0u;
    for (int i = tid; i < HCHUNK; i += 256) xs[i] = g_x[h0 + i];
    __syncthreads();
    int v = blockIdx.x * 256 + tid;
    if (v >= VOCAB) return;
    const float* wp = W + (size_t)h0 * VOCAB + v;
    float a0 = 0.f, a1 = 0.f, a2 = 0.f, a3 = 0.f;
    for (int i = 0; i < HCHUNK; i += 16) {
        float w[16];
#pragma unroll
        for (int j = 0; j < 16; j++) w[j] = __ldcs(wp + (size_t)j * VOCAB);
        wp += 16 * (size_t)VOCAB;
#pragma unroll
        for (int j = 0; j < 16; j += 4) {
            a0 += xs[i + j]     * w[j];
            a1 += xs[i + j + 1] * w[j + 1];
            a2 += xs[i + j + 2] * w[j + 2];
            a3 += xs[i + j + 3] * w[j + 3];
        }
    }
    g_part[hb * VOCAB + v] = (a0 + a1) + (a2 + a3);
}

// ---------------- combine + penalty + histogram (fused) ----------------
__global__ void fuse_kernel(const float* __restrict__ pen) {
    int v = blockIdx.x * 256 + threadIdx.x;
    if (v >= VOCAB) return;
    float s = (g_part[v] + g_part[VOCAB + v]) +
              (g_part[2 * VOCAB + v] + g_part[3 * VOCAB + v]);
    if ((g_bitmap[v >> 5] >> (v & 31)) & 1u) {
        float p = pen[0];
        s = (s < 0.f) ? s * p : s / p;
    }
    g_logits[v] = s;
    atomicAdd(&g_hist[fkey(s) >> 16], 1u);
}

// ---------------- threshold bin (one small block) ----------------
__global__ void thresh_kernel() {
    __shared__ unsigned int cs[1024];
    int tid = threadIdx.x;
    unsigned s = 0;
    int base = tid * 64;
    for (int j = 0; j < 64; j++) s += g_hist[base + j];
    cs[tid] = s;
    __syncthreads();
    if (tid == 0) {
        unsigned acc = 0;
        int t = 1023;
        for (; t > 0; --t) {
            if (acc + cs[t] >= (unsigned)TOPK) break;
            acc += cs[t];
        }
        int B = t * 64;
        for (int b = t * 64 + 63; b >= t * 64; --b) {
            unsigned c = g_hist[b];
            if (acc + c >= (unsigned)TOPK) { B = b; break; }
            acc += c;
        }
        g_Bf = (unsigned)B << 16;
        g_cnt = 0;
    }
}

// ---------------- parallel candidate collection ----------------
__global__ void collect_kernel() {
    int v = blockIdx.x * 256 + threadIdx.x;
    if (v >= VOCAB) return;
    float f = g_logits[v];
    if (fkey(f) >= g_Bf) {
        int p = atomicAdd(&g_cnt, 1);
        if (p < CAP) { g_cv[p] = f; g_ci[p] = v; }
    }
}

// ---------------- rank-sort + sampling; sampler scratch in SHARED (reg-safe) ----------------
__global__ void __launch_bounds__(1024) sort_sample_kernel(
        const float* __restrict__ tp_,
        const float* __restrict__ temp_,
        float* __restrict__ out, int out_size) {
    __shared__ float cv[CAP];
    __shared__ int   ci[CAP];
    __shared__ float tv[TOPK];
    __shared__ int   tix[TOPK];
    __shared__ float sx[TOPK];
    __shared__ float sp[TOPK];
    int tid = threadIdx.x;
    int n = min(g_cnt, CAP);
    for (int i = tid; i < n; i += 1024) { cv[i] = g_cv[i]; ci[i] = g_ci[i]; }
    __syncthreads();
    for (int i = tid; i < n; i += 1024) {
        float v = cv[i]; int ix = ci[i];
        int r = 0;
        for (int j = 0; j < n; j++) {
            float vj = cv[j];
            if (vj > v || (vj == v && ci[j] < ix)) r++;
        }
        if (r < TOPK) { tv[r] = v; tix[r] = ix; }
    }
    __syncthreads();
    // scaled logits + first softmax numerators in parallel
    if (tid < TOPK) {
        float t = temp_[0];
        float xv = tv[tid] / t;
        sx[tid] = xv;
    }
    __syncthreads();
    if (tid < TOPK) sp[tid] = expf(sx[tid] - sx[0]);
    __syncthreads();
    if (tid == 0) {                      // serial cumsum / mask / renorm on shared
        float tp = tp_[0];
        float m = sx[0];
        float s = 0.f;
        for (int i = 0; i < TOPK; i++) s += sp[i];
        float cum = 0.f, s2 = 0.f;
        for (int i = 0; i < TOPK; i++) {
            cum += sp[i] / s;
            bool keep = (cum < tp) || (i < MINKEEP);
            float f = keep ? sx[i] : -1000.0f;
            float e = expf(f - m);
            sp[i] = e;                   // reuse as filtered numerators
            s2 += e;
        }
        sx[0] = s2;                      // stash denominator
    }
    __syncthreads();
    if (tid < TOPK) out[tid] = sp[tid] / sx[0];
    if (out_size >= 2 * TOPK && tid < TOPK) out[TOPK + tid] = (float)tix[tid];
}

extern "C" void kernel_launch(void* const* d_in, const int* in_sizes, int n_in,
                              void* d_out, int out_size) {
    const float* hidden = (const float*)d_in[0];
    const void*  ids    = d_in[1];
    const float* top_p  = (const float*)d_in[2];
    const float* temp   = (const float*)d_in[3];
    const float* pen    = (const float*)d_in[4];
    const float* gamma  = (const float*)d_in[5];
    const float* beta   = (const float*)d_in[6];
    const float* W      = (const float*)d_in[7];
    float* out = (float*)d_out;

    ln_kernel<<<1, 1024>>>(hidden, gamma, beta, ids);
    dim3 g(NVBLK, HSPLIT);
    gemv_kernel<<<g, 256>>>(W);
    fuse_kernel<<<NVBLK, 256>>>(pen);
    thresh_kernel<<<1, 1024>>>();
    collect_kernel<<<NVBLK, 256>>>();
    sort_sample_kernel<<<1, 1024>>>(top_p, temp, out, out_size);
}

// round 4
// speedup vs baseline: 1.0811x; 1.0099x over previous
#include <cuda_runtime.h>
#include <cstdint>

#define HDIM 4096
#define VOCAB 50257
#define SEQL 2048
#define TOPK 50
#define MINKEEP 5
#define HSPLIT 4
#define HCHUNK (HDIM / HSPLIT)          // 1024
#define NVBLK ((VOCAB + 255) / 256)     // 197
#define CAP 2048
#define BMW ((VOCAB + 31) / 32)         // bitmap words

__device__ float g_x[HDIM];
__device__ float g_part[HSPLIT * VOCAB];
__device__ float g_logits[VOCAB];
__device__ unsigned int g_hist[65536];
__device__ unsigned int g_bitmap[BMW];
__device__ unsigned int g_Bf;
__device__ int g_cnt;
__device__ float g_cv[CAP];
__device__ int   g_ci[CAP];

__device__ __forceinline__ unsigned int fkey(float f) {
    unsigned int u = __float_as_uint(f);
    return (u & 0x80000000u) ? ~u : (u | 0x80000000u);
}

// ---------------- LayerNorm + penalty bitmap build (one block) ----------------
__global__ void ln_kernel(const float* __restrict__ hin,
                          const float* __restrict__ gamma,
                          const float* __restrict__ beta,
                          const void* __restrict__ ids_raw) {
    __shared__ float xs[HDIM];
    __shared__ float red[1024];
    __shared__ int bad;
    int tid = threadIdx.x;
    for (int i = tid; i < BMW; i += 1024) g_bitmap[i] = 0u;
    if (tid == 0) bad = 0;

    float s = 0.f;
    for (int i = tid; i < HDIM; i += 1024) { float v = hin[i]; xs[i] = v; s += v; }
    red[tid] = s; __syncthreads();
    for (int o = 512; o > 0; o >>= 1) { if (tid < o) red[tid] += red[tid + o]; __syncthreads(); }
    float mu = red[0] / HDIM;
    __syncthreads();
    float sq = 0.f;
    for (int i = tid; i < HDIM; i += 1024) { float d = xs[i] - mu; sq += d * d; }
    red[tid] = sq; __syncthreads();
    for (int o = 512; o > 0; o >>= 1) { if (tid < o) red[tid] += red[tid + o]; __syncthreads(); }
    float rstd = rsqrtf(red[0] / HDIM + 1e-5f);
    for (int i = tid; i < HDIM; i += 1024)
        g_x[i] = (xs[i] - mu) * rstd * gamma[i] + beta[i];

    // ---- int64-vs-int32 detection (first 8KB valid under both) ----
    const long long* ll = (const long long*)ids_raw;
    long long probe = ll[tid];
    if (probe < 0 || probe >= VOCAB) atomicOr(&bad, 1);
    __syncthreads();
    int is64 = (bad == 0);
    long long id0, id1;
    if (is64) { id0 = ll[tid]; id1 = ll[tid + 1024]; }
    else {
        const int* ii = (const int*)ids_raw;
        id0 = ii[tid]; id1 = ii[tid + 1024];
    }
    atomicOr(&g_bitmap[(int)(id0 >> 5)], 1u << ((int)id0 & 31));
    atomicOr(&g_bitmap[(int)(id1 >> 5)], 1u << ((int)id1 & 31));
}

// ---------------- GEMV: 16 loads in flight per thread, single wave ----------------
__global__ void __launch_bounds__(256, 6) gemv_kernel(const float* __restrict__ W) {
    __shared__ float xs[HCHUNK];
    int tid = threadIdx.x;
    int hb = blockIdx.y;
    int h0 = hb * HCHUNK;
    // fused hist zeroing (hist consumed 2 launches later)
    int gb = (hb * gridDim.x + blockIdx.x) * 256 + tid;
    if (gb < 65536) g_hist[gb] = 0u;
    for (int i = tid; i < HCHUNK; i += 256) xs[i] = g_x[h0 + i];
    __syncthreads();
    int v = blockIdx.x * 256 + tid;
    if (v >= VOCAB) return;
    const float* wp = W + (size_t)h0 * VOCAB + v;
    float a0 = 0.f, a1 = 0.f, a2 = 0.f, a3 = 0.f;
    for (int i = 0; i < HCHUNK; i += 16) {
        float w[16];
#pragma unroll
        for (int j = 0; j < 16; j++) w[j] = __ldcs(wp + (size_t)j * VOCAB);
        wp += 16 * (size_t)VOCAB;
#pragma unroll
        for (int j = 0; j < 16; j += 4) {
            a0 += xs[i + j]     * w[j];
            a1 += xs[i + j + 1] * w[j + 1];
            a2 += xs[i + j + 2] * w[j + 2];
            a3 += xs[i + j + 3] * w[j + 3];
        }
    }
    g_part[hb * VOCAB + v] = (a0 + a1) + (a2 + a3);
}

// ---------------- combine + penalty + histogram (fused) ----------------
__global__ void fuse_kernel(const float* __restrict__ pen) {
    int v = blockIdx.x * 256 + threadIdx.x;
    if (v >= VOCAB) return;
    float s = (g_part[v] + g_part[VOCAB + v]) +
              (g_part[2 * VOCAB + v] + g_part[3 * VOCAB + v]);
    if ((g_bitmap[v >> 5] >> (v & 31)) & 1u) {
        float p = pen[0];
        s = (s < 0.f) ? s * p : s / p;
    }
    g_logits[v] = s;
    atomicAdd(&g_hist[fkey(s) >> 16], 1u);
}

// ---------------- threshold bin (one small block) ----------------
__global__ void thresh_kernel() {
    __shared__ unsigned int cs[1024];
    int tid = threadIdx.x;
    unsigned s = 0;
    int base = tid * 64;
    for (int j = 0; j < 64; j++) s += g_hist[base + j];
    cs[tid] = s;
    __syncthreads();
    if (tid == 0) {
        unsigned acc = 0;
        int t = 1023;
        for (; t > 0; --t) {
            if (acc + cs[t] >= (unsigned)TOPK) break;
            acc += cs[t];
        }
        int B = t * 64;
        for (int b = t * 64 + 63; b >= t * 64; --b) {
            unsigned c = g_hist[b];
            if (acc + c >= (unsigned)TOPK) { B = b; break; }
            acc += c;
        }
        g_Bf = (unsigned)B << 16;
        g_cnt = 0;
    }
}

// ---------------- parallel candidate collection ----------------
__global__ void collect_kernel() {
    int v = blockIdx.x * 256 + threadIdx.x;
    if (v >= VOCAB) return;
    float f = g_logits[v];
    if (fkey(f) >= g_Bf) {
        int p = atomicAdd(&g_cnt, 1);
        if (p < CAP) { g_cv[p] = f; g_ci[p] = v; }
    }
}

// ---------------- rank-sort + sampling; sampler scratch in SHARED (reg-safe) ----------------
__global__ void __launch_bounds__(1024) sort_sample_kernel(
        const float* __restrict__ tp_,
        const float* __restrict__ temp_,
        float* __restrict__ out, int out_size) {
    __shared__ float cv[CAP];
    __shared__ int   ci[CAP];
    __shared__ float tv[TOPK];
    __shared__ int   tix[TOPK];
    __shared__ float sx[TOPK];
    __shared__ float sp[TOPK];
    int tid = threadIdx.x;
    int n = min(g_cnt, CAP);
    for (int i = tid; i < n; i += 1024) { cv[i] = g_cv[i]; ci[i] = g_ci[i]; }
    __syncthreads();
    for (int i = tid; i < n; i += 1024) {
        float v = cv[i]; int ix = ci[i];
        int r = 0;
        for (int j = 0; j < n; j++) {
            float vj = cv[j];
            if (vj > v || (vj == v && ci[j] < ix)) r++;
        }
        if (r < TOPK) { tv[r] = v; tix[r] = ix; }
    }
    __syncthreads();
    // scaled logits + first softmax numerators in parallel
    if (tid < TOPK) {
        float t = temp_[0];
        float xv = tv[tid] / t;
        sx[tid] = xv;
    }
    __syncthreads();
    if (tid < TOPK) sp[tid] = expf(sx[tid] - sx[0]);
    __syncthreads();
    if (tid == 0) {                      // serial cumsum / mask / renorm on shared
        float tp = tp_[0];
        float m = sx[0];
        float s = 0.f;
        for (int i = 0; i < TOPK; i++) s += sp[i];
        float cum = 0.f, s2 = 0.f;
        for (int i = 0; i < TOPK; i++) {
            cum += sp[i] / s;
            bool keep = (cum < tp) || (i < MINKEEP);
            float f = keep ? sx[i] : -1000.0f;
            float e = expf(f - m);
            sp[i] = e;                   // reuse as filtered numerators
            s2 += e;
        }
        sx[0] = s2;                      // stash denominator
    }
    __syncthreads();
    if (tid < TOPK) out[tid] = sp[tid] / sx[0];
    if (out_size >= 2 * TOPK && tid < TOPK) out[TOPK + tid] = (float)tix[tid];
}

extern "C" void kernel_launch(void* const* d_in, const int* in_sizes, int n_in,
                              void* d_out, int out_size) {
    const float* hidden = (const float*)d_in[0];
    const void*  ids    = d_in[1];
    const float* top_p  = (const float*)d_in[2];
    const float* temp   = (const float*)d_in[3];
    const float* pen    = (const float*)d_in[4];
    const float* gamma  = (const float*)d_in[5];
    const float* beta   = (const float*)d_in[6];
    const float* W      = (const float*)d_in[7];
    float* out = (float*)d_out;

    ln_kernel<<<1, 1024>>>(hidden, gamma, beta, ids);
    dim3 g(NVBLK, HSPLIT);
    gemv_kernel<<<g, 256>>>(W);
    fuse_kernel<<<NVBLK, 256>>>(pen);
    thresh_kernel<<<1, 1024>>>();
    collect_kernel<<<NVBLK, 256>>>();
    sort_sample_kernel<<<1, 1024>>>(top_p, temp, out, out_size);
}

// round 5
// speedup vs baseline: 1.3177x; 1.2189x over previous
#include <cuda_runtime.h>
#include <cstdint>

#define HDIM 4096
#define VOCAB 50257
#define SEQL 2048
#define TOPK 50
#define MINKEEP 5
#define HSPLIT 4
#define HCHUNK (HDIM / HSPLIT)          // 1024
#define NVBLK ((VOCAB + 255) / 256)     // 197
#define CAP 2048
#define BMW ((VOCAB + 31) / 32)         // bitmap words

__device__ float g_x[HDIM];
__device__ float g_part[HSPLIT * VOCAB];
__device__ float g_logits[VOCAB];
__device__ unsigned int g_hist[65536];
__device__ unsigned int g_coarse[1024];
__device__ unsigned int g_bitmap[BMW];
__device__ unsigned int g_Bf;
__device__ int g_cnt;
__device__ float g_cv[CAP];
__device__ int   g_ci[CAP];

__device__ __forceinline__ unsigned int fkey(float f) {
    unsigned int u = __float_as_uint(f);
    return (u & 0x80000000u) ? ~u : (u | 0x80000000u);
}

// ---------------- LayerNorm + penalty bitmap build (one block) ----------------
__global__ void ln_kernel(const float* __restrict__ hin,
                          const float* __restrict__ gamma,
                          const float* __restrict__ beta,
                          const void* __restrict__ ids_raw) {
    __shared__ float xs[HDIM];
    __shared__ float red[1024];
    __shared__ int bad;
    int tid = threadIdx.x;
    for (int i = tid; i < BMW; i += 1024) g_bitmap[i] = 0u;
    if (tid == 0) bad = 0;

    float s = 0.f;
    for (int i = tid; i < HDIM; i += 1024) { float v = hin[i]; xs[i] = v; s += v; }
    red[tid] = s; __syncthreads();
    for (int o = 512; o > 0; o >>= 1) { if (tid < o) red[tid] += red[tid + o]; __syncthreads(); }
    float mu = red[0] / HDIM;
    __syncthreads();
    float sq = 0.f;
    for (int i = tid; i < HDIM; i += 1024) { float d = xs[i] - mu; sq += d * d; }
    red[tid] = sq; __syncthreads();
    for (int o = 512; o > 0; o >>= 1) { if (tid < o) red[tid] += red[tid + o]; __syncthreads(); }
    float rstd = rsqrtf(red[0] / HDIM + 1e-5f);
    for (int i = tid; i < HDIM; i += 1024)
        g_x[i] = (xs[i] - mu) * rstd * gamma[i] + beta[i];

    // ---- int64-vs-int32 detection (first 8KB valid under both) ----
    const long long* ll = (const long long*)ids_raw;
    long long probe = ll[tid];
    if (probe < 0 || probe >= VOCAB) atomicOr(&bad, 1);
    __syncthreads();
    int is64 = (bad == 0);
    long long id0, id1;
    if (is64) { id0 = ll[tid]; id1 = ll[tid + 1024]; }
    else {
        const int* ii = (const int*)ids_raw;
        id0 = ii[tid]; id1 = ii[tid + 1024];
    }
    atomicOr(&g_bitmap[(int)(id0 >> 5)], 1u << ((int)id0 & 31));
    atomicOr(&g_bitmap[(int)(id1 >> 5)], 1u << ((int)id1 & 31));
}

// ---------------- GEMV: 16 loads in flight per thread, single wave ----------------
__global__ void __launch_bounds__(256, 6) gemv_kernel(const float* __restrict__ W) {
    __shared__ float xs[HCHUNK];
    int tid = threadIdx.x;
    int hb = blockIdx.y;
    int h0 = hb * HCHUNK;
    // fused zeroing of fine + coarse histograms (consumed 2 launches later)
    int gb = (hb * gridDim.x + blockIdx.x) * 256 + tid;
    if (gb < 65536) g_hist[gb] = 0u;
    if (gb < 1024)  g_coarse[gb] = 0u;
    for (int i = tid; i < HCHUNK; i += 256) xs[i] = g_x[h0 + i];
    __syncthreads();
    int v = blockIdx.x * 256 + tid;
    if (v >= VOCAB) return;
    const float* wp = W + (size_t)h0 * VOCAB + v;
    float a0 = 0.f, a1 = 0.f, a2 = 0.f, a3 = 0.f;
    for (int i = 0; i < HCHUNK; i += 16) {
        float w[16];
#pragma unroll
        for (int j = 0; j < 16; j++) w[j] = __ldcs(wp + (size_t)j * VOCAB);
        wp += 16 * (size_t)VOCAB;
#pragma unroll
        for (int j = 0; j < 16; j += 4) {
            a0 += xs[i + j]     * w[j];
            a1 += xs[i + j + 1] * w[j + 1];
            a2 += xs[i + j + 2] * w[j + 2];
            a3 += xs[i + j + 3] * w[j + 3];
        }
    }
    g_part[hb * VOCAB + v] = (a0 + a1) + (a2 + a3);
}

// ---------------- combine + penalty + two-level histogram (fused) ----------------
__global__ void fuse_kernel(const float* __restrict__ pen) {
    int v = blockIdx.x * 256 + threadIdx.x;
    if (v >= VOCAB) return;
    float s = (g_part[v] + g_part[VOCAB + v]) +
              (g_part[2 * VOCAB + v] + g_part[3 * VOCAB + v]);
    if ((g_bitmap[v >> 5] >> (v & 31)) & 1u) {
        float p = pen[0];
        s = (s < 0.f) ? s * p : s / p;
    }
    g_logits[v] = s;
    unsigned k = fkey(s);
    atomicAdd(&g_hist[k >> 16], 1u);
    atomicAdd(&g_coarse[k >> 22], 1u);
}

// ---------------- threshold: coarse scan (1024 LDG) + one 64-bin fine chunk ----------------
__global__ void thresh_kernel() {
    __shared__ unsigned cs[1024];
    __shared__ unsigned ws[32];
    __shared__ unsigned fb[64];
    __shared__ int sh_t;
    __shared__ unsigned sh_acc;
    int tid = threadIdx.x;
    unsigned c = g_coarse[tid];
    cs[tid] = c;
    unsigned s = c;
    for (int o = 16; o > 0; o >>= 1) s += __shfl_down_sync(0xffffffffu, s, o);
    if ((tid & 31) == 0) ws[tid >> 5] = s;
    __syncthreads();
    if (tid == 0) {
        unsigned acc = 0;
        int w = 31;
        for (; w > 0; --w) {
            if (acc + ws[w] >= (unsigned)TOPK) break;
            acc += ws[w];
        }
        int t = w * 32;
        for (int b = w * 32 + 31; b >= w * 32; --b) {
            unsigned cc = cs[b];
            if (acc + cc >= (unsigned)TOPK) { t = b; break; }
            acc += cc;
        }
        sh_t = t; sh_acc = acc;
    }
    __syncthreads();
    int t = sh_t;
    if (tid < 64) fb[tid] = g_hist[t * 64 + tid];
    __syncthreads();
    if (tid == 0) {
        unsigned acc = sh_acc;
        int B = t * 64;
        for (int b = 63; b >= 0; --b) {
            unsigned cc = fb[b];
            if (acc + cc >= (unsigned)TOPK) { B = t * 64 + b; break; }
            acc += cc;
        }
        g_Bf = (unsigned)B << 16;
        g_cnt = 0;
    }
}

// ---------------- parallel candidate collection ----------------
__global__ void collect_kernel() {
    int v = blockIdx.x * 256 + threadIdx.x;
    if (v >= VOCAB) return;
    float f = g_logits[v];
    if (fkey(f) >= g_Bf) {
        int p = atomicAdd(&g_cnt, 1);
        if (p < CAP) { g_cv[p] = f; g_ci[p] = v; }
    }
}

// ---------------- rank-sort + sampling; sampler scratch in SHARED (reg-safe) ----------------
__global__ void __launch_bounds__(1024) sort_sample_kernel(
        const float* __restrict__ tp_,
        const float* __restrict__ temp_,
        float* __restrict__ out, int out_size) {
    __shared__ float cv[CAP];
    __shared__ int   ci[CAP];
    __shared__ float tv[TOPK];
    __shared__ int   tix[TOPK];
    __shared__ float sx[TOPK];
    __shared__ float sp[TOPK];
    int tid = threadIdx.x;
    int n = min(g_cnt, CAP);
    for (int i = tid; i < n; i += 1024) { cv[i] = g_cv[i]; ci[i] = g_ci[i]; }
    __syncthreads();
    for (int i = tid; i < n; i += 1024) {
        float v = cv[i]; int ix = ci[i];
        int r = 0;
        for (int j = 0; j < n; j++) {
            float vj = cv[j];
            if (vj > v || (vj == v && ci[j] < ix)) r++;
        }
        if (r < TOPK) { tv[r] = v; tix[r] = ix; }
    }
    __syncthreads();
    if (tid < TOPK) {
        float t = temp_[0];
        sx[tid] = tv[tid] / t;
    }
    __syncthreads();
    if (tid < TOPK) sp[tid] = expf(sx[tid] - sx[0]);
    __syncthreads();
    if (tid == 0) {
        float tp = tp_[0];
        float m = sx[0];
        float s = 0.f;
        for (int i = 0; i < TOPK; i++) s += sp[i];
        float cum = 0.f, s2 = 0.f;
        for (int i = 0; i < TOPK; i++) {
            cum += sp[i] / s;
            bool keep = (cum < tp) || (i < MINKEEP);
            float f = keep ? sx[i] : -1000.0f;
            float e = expf(f - m);
            sp[i] = e;
            s2 += e;
        }
        sx[0] = s2;
    }
    __syncthreads();
    if (tid < TOPK) out[tid] = sp[tid] / sx[0];
    if (out_size >= 2 * TOPK && tid < TOPK) out[TOPK + tid] = (float)tix[tid];
}

extern "C" void kernel_launch(void* const* d_in, const int* in_sizes, int n_in,
                              void* d_out, int out_size) {
    const float* hidden = (const float*)d_in[0];
    const void*  ids    = d_in[1];
    const float* top_p  = (const float*)d_in[2];
    const float* temp   = (const float*)d_in[3];
    const float* pen    = (const float*)d_in[4];
    const float* gamma  = (const float*)d_in[5];
    const float* beta   = (const float*)d_in[6];
    const float* W      = (const float*)d_in[7];
    float* out = (float*)d_out;

    ln_kernel<<<1, 1024>>>(hidden, gamma, beta, ids);
    dim3 g(NVBLK, HSPLIT);
    gemv_kernel<<<g, 256>>>(W);
    fuse_kernel<<<NVBLK, 256>>>(pen);
    thresh_kernel<<<1, 1024>>>();
    collect_kernel<<<NVBLK, 256>>>();
    sort_sample_kernel<<<1, 1024>>>(top_p, temp, out, out_size);
}